// round 1
// baseline (speedup 1.0000x reference)
#include <cuda_runtime.h>
#include <math.h>
#include <stdint.h>

#define BATCH 8
#define ANUM 15
#define HH 100
#define WW 168
#define NPER (ANUM*HH*WW)      // 252000
#define PRE 2000
#define POST 1000
#define CAND_CAP 4096
#define NWORDS 32              // ceil(PRE/64)
#define STRIDEF 8.0f

// ---------------- scratch (no allocations allowed) ----------------
__device__ unsigned int      g_hist[BATCH][256];
__device__ unsigned int      g_prefix[BATCH];
__device__ int               g_krem[BATCH];
__device__ unsigned long long g_cand[BATCH][CAND_CAP];
__device__ int               g_ccnt[BATCH];
__device__ int               g_tidx[BATCH][PRE];
__device__ float             g_tsc[BATCH][PRE];
__device__ float4            g_box[BATCH][PRE];
__device__ unsigned char     g_val[BATCH][PRE];
__device__ unsigned long long g_mask[BATCH][PRE][NWORDS];   // 4 MB
__device__ unsigned char     g_keep[BATCH][PRE];

// ---------------- init ----------------
__global__ void k_init() {
    int img = blockIdx.x;
    g_hist[img][threadIdx.x] = 0u;
    if (threadIdx.x == 0) {
        g_ccnt[img] = 0;
        g_prefix[img] = 0u;
        g_krem[img] = PRE;
    }
}

// ---------------- radix-select histogram pass ----------------
__global__ void k_hist(const float* __restrict__ cls, int pass) {
    int img = blockIdx.y;
    __shared__ unsigned int sh[256];
    for (int t = threadIdx.x; t < 256; t += blockDim.x) sh[t] = 0u;
    __syncthreads();
    unsigned int pref = g_prefix[img];
    int shp = 32 - 8 * pass;     // prefix shift (unused when pass==0)
    int shb = 24 - 8 * pass;     // byte shift
    const float* p = cls + (size_t)img * NPER;
    for (int i = blockIdx.x * blockDim.x + threadIdx.x; i < NPER; i += gridDim.x * blockDim.x) {
        unsigned int bits = __float_as_uint(p[i]);
        bool ok = (pass == 0) || ((bits >> shp) == pref);
        if (ok) atomicAdd(&sh[(bits >> shb) & 0xFFu], 1u);
    }
    __syncthreads();
    for (int t = threadIdx.x; t < 256; t += blockDim.x)
        if (sh[t]) atomicAdd(&g_hist[img][t], sh[t]);
}

__global__ void k_select() {
    int img = blockIdx.x;
    __shared__ unsigned int h[256];
    int t = threadIdx.x;
    h[t] = g_hist[img][t];
    __syncthreads();
    if (t == 0) {
        int k = g_krem[img];
        unsigned int cum = 0;
        int v;
        for (v = 255; v >= 1; v--) {
            unsigned int c = h[v];
            if (cum + c >= (unsigned int)k) break;
            cum += c;
        }
        g_prefix[img] = (g_prefix[img] << 8) | (unsigned int)v;
        g_krem[img] = k - (int)cum;
    }
    __syncthreads();
    g_hist[img][t] = 0u;   // reset for next pass
}

// ---------------- compact candidates >= threshold ----------------
__global__ void k_compact(const float* __restrict__ cls) {
    int img = blockIdx.y;
    unsigned int T = g_prefix[img];
    const float* p = cls + (size_t)img * NPER;
    for (int i = blockIdx.x * blockDim.x + threadIdx.x; i < NPER; i += gridDim.x * blockDim.x) {
        unsigned int bits = __float_as_uint(p[i]);
        if (bits >= T) {
            int a = i / (HH * WW);
            int rem = i - a * (HH * WW);          // h*W + w
            int r = rem * ANUM + a;                // flattened (h,w,a) index
            int pos = atomicAdd(&g_ccnt[img], 1);
            if (pos < CAND_CAP)
                g_cand[img][pos] = ((unsigned long long)bits << 32) | (unsigned int)(~r);
        }
    }
}

// ---------------- bitonic sort (descending) of 4096 keys ----------------
__global__ void k_sort() {
    int img = blockIdx.x;
    __shared__ unsigned long long s[CAND_CAP];
    int cnt = g_ccnt[img];
    if (cnt > CAND_CAP) cnt = CAND_CAP;
    for (int i = threadIdx.x; i < CAND_CAP; i += blockDim.x)
        s[i] = (i < cnt) ? g_cand[img][i] : 0ull;
    __syncthreads();
    for (int k = 2; k <= CAND_CAP; k <<= 1) {
        for (int j = k >> 1; j > 0; j >>= 1) {
            for (int i = threadIdx.x; i < CAND_CAP; i += blockDim.x) {
                int ixj = i ^ j;
                if (ixj > i) {
                    unsigned long long a = s[i], b = s[ixj];
                    bool descSeg = ((i & k) == 0);
                    if (descSeg ? (a < b) : (a > b)) { s[i] = b; s[ixj] = a; }
                }
            }
            __syncthreads();
        }
    }
    for (int i = threadIdx.x; i < PRE; i += blockDim.x) {
        unsigned long long key = s[i];
        g_tidx[img][i] = (int)(~(unsigned int)key);
        g_tsc[img][i] = __uint_as_float((unsigned int)(key >> 32));
    }
}

// ---------------- bbox transform + clip + validity ----------------
__global__ void k_props(const float* __restrict__ pred,
                        const float* __restrict__ iminfo,
                        const float* __restrict__ anchors) {
    int img = blockIdx.y;
    int i = blockIdx.x * blockDim.x + threadIdx.x;
    if (i >= PRE) return;
    int r = g_tidx[img][i];
    int a = r % ANUM;
    int t = r / ANUM;
    int w = t % WW;
    int h = t / WW;

    float sx = (float)w * STRIDEF;
    float sy = (float)h * STRIDEF;
    float ax1 = __fadd_rn(anchors[a * 4 + 0], sx);
    float ay1 = __fadd_rn(anchors[a * 4 + 1], sy);
    float ax2 = __fadd_rn(anchors[a * 4 + 2], sx);
    float ay2 = __fadd_rn(anchors[a * 4 + 3], sy);

    float ws = __fadd_rn(__fsub_rn(ax2, ax1), 1.0f);
    float hs = __fadd_rn(__fsub_rn(ay2, ay1), 1.0f);
    float cx = __fadd_rn(ax1, __fmul_rn(0.5f, ws));
    float cy = __fadd_rn(ay1, __fmul_rn(0.5f, hs));

    size_t base = (((size_t)img * (4 * ANUM) + 4 * a) * HH + h) * WW + w;
    float dx = pred[base];
    float dy = pred[base + (size_t)HH * WW];
    float dw = pred[base + 2 * (size_t)HH * WW];
    float dh = pred[base + 3 * (size_t)HH * WW];
    const float XCLIP = 4.135166556742356f; // log(1000/16)
    dw = fminf(dw, XCLIP);
    dh = fminf(dh, XCLIP);

    float pcx = __fadd_rn(__fmul_rn(dx, ws), cx);
    float pcy = __fadd_rn(__fmul_rn(dy, hs), cy);
    float ew = (float)exp((double)dw);   // double exp -> correctly rounded f32
    float eh = (float)exp((double)dh);
    float pw = __fmul_rn(ew, ws);
    float ph = __fmul_rn(eh, hs);

    float x1 = __fsub_rn(pcx, __fmul_rn(0.5f, pw));
    float y1 = __fsub_rn(pcy, __fmul_rn(0.5f, ph));
    float x2 = __fsub_rn(__fadd_rn(pcx, __fmul_rn(0.5f, pw)), 1.0f);
    float y2 = __fsub_rn(__fadd_rn(pcy, __fmul_rn(0.5f, ph)), 1.0f);

    float im_h = iminfo[img * 3 + 0];
    float im_w = iminfo[img * 3 + 1];
    float scale = iminfo[img * 3 + 2];
    float wmax = __fsub_rn(im_w, 1.0f);
    float hmax = __fsub_rn(im_h, 1.0f);
    x1 = fminf(fmaxf(x1, 0.0f), wmax);
    y1 = fminf(fmaxf(y1, 0.0f), hmax);
    x2 = fminf(fmaxf(x2, 0.0f), wmax);
    y2 = fminf(fmaxf(y2, 0.0f), hmax);

    float ws2 = __fadd_rn(__fsub_rn(x2, x1), 1.0f);
    float hs2 = __fadd_rn(__fsub_rn(y2, y1), 1.0f);
    float ms = __fmul_rn(0.0f, scale);   // MIN_SIZE = 0
    bool valid = (ws2 >= ms) & (hs2 >= ms)
               & (__fadd_rn(x1, __fmul_rn(ws2, 0.5f)) < im_w)
               & (__fadd_rn(y1, __fmul_rn(hs2, 0.5f)) < im_h);

    g_box[img][i] = make_float4(x1, y1, x2, y2);
    g_val[img][i] = valid ? 1 : 0;
}

// ---------------- NMS pairwise bitmask ----------------
__device__ __forceinline__ float boxArea(float4 b) {
    return __fmul_rn(__fadd_rn(__fsub_rn(b.z, b.x), 1.0f),
                     __fadd_rn(__fsub_rn(b.w, b.y), 1.0f));
}

__global__ void k_nmsmask() {
    int img = blockIdx.z;
    int rb = blockIdx.y;
    int cb = blockIdx.x;
    int i = rb * 64 + threadIdx.x;
    if (cb < rb) {                 // strictly below diagonal: no j > i here
        if (i < PRE) g_mask[img][i][cb] = 0ull;
        return;
    }
    __shared__ float4 cbox[64];
    __shared__ float carea[64];
    int j0 = cb * 64;
    int jj = threadIdx.x;
    if (j0 + jj < PRE) {
        float4 b = g_box[img][j0 + jj];
        cbox[jj] = b;
        carea[jj] = boxArea(b);
    } else {
        cbox[jj] = make_float4(0, 0, 0, 0);
        carea[jj] = 0.f;
    }
    __syncthreads();
    if (i >= PRE) return;
    float4 bi = g_box[img][i];
    float ai = boxArea(bi);
    unsigned long long bits = 0ull;
    #pragma unroll 8
    for (int q = 0; q < 64; q++) {
        int j = j0 + q;
        if (j <= i || j >= PRE) continue;
        float4 bj = cbox[q];
        float xx1 = fmaxf(bi.x, bj.x);
        float yy1 = fmaxf(bi.y, bj.y);
        float xx2 = fminf(bi.z, bj.z);
        float yy2 = fminf(bi.w, bj.w);
        float iw = fmaxf(__fadd_rn(__fsub_rn(xx2, xx1), 1.0f), 0.0f);
        float ih = fmaxf(__fadd_rn(__fsub_rn(yy2, yy1), 1.0f), 0.0f);
        float inter = __fmul_rn(iw, ih);
        float denom = __fsub_rn(__fadd_rn(ai, carea[q]), inter);
        float iou = __fdiv_rn(inter, denom);
        if (iou > 0.7f) bits |= (1ull << q);
    }
    g_mask[img][i][cb] = bits;
}

// ---------------- sequential greedy reduce (one warp / image) ----------------
__global__ void k_reduce() {
    int img = blockIdx.x;
    int t = threadIdx.x;               // 0..31
    unsigned long long rem = 0ull;     // suppression word t
    for (int i = 0; i < PRE; i++) {
        unsigned long long m = g_mask[img][i][t];   // prefetched, indep of chain
        unsigned char v = g_val[img][i];
        unsigned long long w = __shfl_sync(0xffffffffu, rem, i >> 6);
        bool sup = (w >> (i & 63)) & 1ull;
        bool keep = v && !sup;
        if (keep) rem |= m;
        if (t == 0) g_keep[img][i] = keep ? 1 : 0;
    }
}

// ---------------- stable compaction + output ----------------
__global__ void k_out(float* __restrict__ out) {
    int img = blockIdx.x;
    __shared__ int pos[2048];
    int tid = threadIdx.x;             // 1024 threads
    pos[tid]        = (tid < PRE) ? (int)g_keep[img][tid] : 0;
    pos[tid + 1024] = (tid + 1024 < PRE) ? (int)g_keep[img][tid + 1024] : 0;
    __syncthreads();
    for (int off = 1; off < 2048; off <<= 1) {
        int a0 = (tid >= off) ? pos[tid - off] : 0;
        int i1 = tid + 1024;
        int a1 = (i1 >= off) ? pos[i1 - off] : 0;
        __syncthreads();
        pos[tid] += a0;
        pos[i1] += a1;
        __syncthreads();
    }
    int total = pos[PRE - 1];
    if (total > POST) total = POST;

    float* rois = out;                         // (B*POST, 5)
    float* probs = out + (size_t)BATCH * POST * 5;

    for (int i = tid; i < PRE; i += 1024) {
        if (g_keep[img][i]) {
            int s = pos[i] - 1;
            if (s < POST) {
                float4 b = g_box[img][i];
                size_t row = (size_t)(img * POST + s) * 5;
                rois[row + 0] = (float)img;
                rois[row + 1] = b.x;
                rois[row + 2] = b.y;
                rois[row + 3] = b.z;
                rois[row + 4] = b.w;
                probs[img * POST + s] = g_tsc[img][i];
            }
        }
    }
    for (int s = total + tid; s < POST; s += 1024) {
        size_t row = (size_t)(img * POST + s) * 5;
        rois[row + 0] = (float)img;
        rois[row + 1] = 0.0f;
        rois[row + 2] = 0.0f;
        rois[row + 3] = 0.0f;
        rois[row + 4] = 0.0f;
        probs[img * POST + s] = 0.0f;
    }
}

// ---------------- launch ----------------
extern "C" void kernel_launch(void* const* d_in, const int* in_sizes, int n_in,
                              void* d_out, int out_size) {
    const float* cls     = (const float*)d_in[0];   // (8,15,100,168)
    const float* pred    = (const float*)d_in[1];   // (8,60,100,168)
    const float* iminfo  = (const float*)d_in[2];   // (8,3)
    const float* anchors = (const float*)d_in[3];   // (15,4)
    float* out = (float*)d_out;

    k_init<<<BATCH, 256>>>();
    for (int p = 0; p < 4; p++) {
        k_hist<<<dim3(120, BATCH), 256>>>(cls, p);
        k_select<<<BATCH, 256>>>();
    }
    k_compact<<<dim3(120, BATCH), 256>>>(cls);
    k_sort<<<BATCH, 1024>>>();
    k_props<<<dim3(2, BATCH), 1000>>>(pred, iminfo, anchors);
    k_nmsmask<<<dim3(NWORDS, NWORDS, BATCH), 64>>>();
    k_reduce<<<BATCH, 32>>>();
    k_out<<<BATCH, 1024>>>(out);
}

// round 2
// speedup vs baseline: 3.3697x; 3.3697x over previous
#include <cuda_runtime.h>
#include <math.h>
#include <stdint.h>

#define BATCH 8
#define ANUM 15
#define HH 100
#define WW 168
#define NPER (ANUM*HH*WW)      // 252000
#define PRE 2000
#define POST 1000
#define CAND_CAP 4096
#define NWORDS 32              // ceil(PRE/64)
#define ROWT 256               // rows per nms tile (4 per thread * 64 threads)
#define STRIDEF 8.0f

// ---------------- scratch (no allocations allowed) ----------------
__device__ unsigned int       g_hist[BATCH][256];
__device__ unsigned int       g_prefix[BATCH];
__device__ int                g_krem[BATCH];
__device__ unsigned long long g_cand[BATCH][CAND_CAP];
__device__ int                g_ccnt[BATCH];
__device__ int                g_tidx[BATCH][PRE];
__device__ float              g_tsc[BATCH][PRE];
__device__ float4             g_box[BATCH][PRE];    // (x1,y1,x2,y2) for output
__device__ float4             g_boxn[BATCH][PRE];   // (-x1,-y1,x2,y2) for IoU
__device__ float              g_area[BATCH][PRE];
__device__ unsigned int       g_valmask32[BATCH][64];
__device__ unsigned long long g_mask[BATCH][PRE][NWORDS];   // 4 MB
__device__ unsigned long long g_keepw[BATCH][NWORDS];

// ---------------- init ----------------
__global__ void k_init() {
    int img = blockIdx.x;
    g_hist[img][threadIdx.x] = 0u;
    if (threadIdx.x == 0) {
        g_ccnt[img] = 0;
        g_prefix[img] = 0u;
        g_krem[img] = PRE;
    }
}

// ---------------- radix-select histogram pass (2 passes: top 16 bits) --------
__global__ void k_hist(const float* __restrict__ cls, int pass) {
    int img = blockIdx.y;
    __shared__ unsigned int sh[256];
    for (int t = threadIdx.x; t < 256; t += blockDim.x) sh[t] = 0u;
    __syncthreads();
    unsigned int pref = g_prefix[img];
    int shp = 32 - 8 * pass;
    int shb = 24 - 8 * pass;
    const float* p = cls + (size_t)img * NPER;
    for (int i = blockIdx.x * blockDim.x + threadIdx.x; i < NPER; i += gridDim.x * blockDim.x) {
        unsigned int bits = __float_as_uint(p[i]);
        bool ok = (pass == 0) || ((bits >> shp) == pref);
        if (ok) atomicAdd(&sh[(bits >> shb) & 0xFFu], 1u);
    }
    __syncthreads();
    for (int t = threadIdx.x; t < 256; t += blockDim.x)
        if (sh[t]) atomicAdd(&g_hist[img][t], sh[t]);
}

__global__ void k_select() {
    int img = blockIdx.x;
    __shared__ unsigned int h[256];
    int t = threadIdx.x;
    h[t] = g_hist[img][t];
    __syncthreads();
    if (t == 0) {
        int k = g_krem[img];
        unsigned int cum = 0;
        int v;
        for (v = 255; v >= 1; v--) {
            unsigned int c = h[v];
            if (cum + c >= (unsigned int)k) break;
            cum += c;
        }
        g_prefix[img] = (g_prefix[img] << 8) | (unsigned int)v;
        g_krem[img] = k - (int)cum;
    }
    __syncthreads();
    g_hist[img][t] = 0u;   // reset for next pass / next replay
}

// ---------------- compact candidates >= 16-bit threshold ----------------
__global__ void k_compact(const float* __restrict__ cls) {
    int img = blockIdx.y;
    unsigned int T = g_prefix[img] << 16;
    const float* p = cls + (size_t)img * NPER;
    for (int i = blockIdx.x * blockDim.x + threadIdx.x; i < NPER; i += gridDim.x * blockDim.x) {
        unsigned int bits = __float_as_uint(p[i]);
        if (bits >= T) {
            int a = i / (HH * WW);
            int rem = i - a * (HH * WW);          // h*W + w
            int r = rem * ANUM + a;                // flattened (h,w,a) index
            int pos = atomicAdd(&g_ccnt[img], 1);
            if (pos < CAND_CAP)
                g_cand[img][pos] = ((unsigned long long)bits << 32) | (unsigned int)(~r);
        }
    }
}

// ---------------- bitonic sort (descending), runtime size 2048/4096 ----------
__global__ void k_sort() {
    int img = blockIdx.x;
    __shared__ unsigned long long s[CAND_CAP];
    int cnt = g_ccnt[img];
    if (cnt > CAND_CAP) cnt = CAND_CAP;
    int n = (cnt <= 2048) ? 2048 : 4096;
    for (int i = threadIdx.x; i < n; i += blockDim.x)
        s[i] = (i < cnt) ? g_cand[img][i] : 0ull;
    __syncthreads();
    for (int k = 2; k <= n; k <<= 1) {
        for (int j = k >> 1; j > 0; j >>= 1) {
            for (int i = threadIdx.x; i < n; i += blockDim.x) {
                int ixj = i ^ j;
                if (ixj > i) {
                    unsigned long long a = s[i], b = s[ixj];
                    bool descSeg = ((i & k) == 0);
                    if (descSeg ? (a < b) : (a > b)) { s[i] = b; s[ixj] = a; }
                }
            }
            __syncthreads();
        }
    }
    for (int i = threadIdx.x; i < PRE; i += blockDim.x) {
        unsigned long long key = s[i];
        g_tidx[img][i] = (int)(~(unsigned int)key);
        g_tsc[img][i] = __uint_as_float((unsigned int)(key >> 32));
    }
}

// ---------------- bbox transform + clip + validity + area/neg precompute -----
__global__ void k_props(const float* __restrict__ pred,
                        const float* __restrict__ iminfo,
                        const float* __restrict__ anchors) {
    int img = blockIdx.y;
    int i = blockIdx.x * blockDim.x + threadIdx.x;     // < 2048

    bool valid = false;
    float x1 = 0.f, y1 = 0.f, x2 = 0.f, y2 = 0.f, area = 0.f;

    if (i < PRE) {
        int r = g_tidx[img][i];
        int a = r % ANUM;
        int t = r / ANUM;
        int w = t % WW;
        int h = t / WW;

        float sx = (float)w * STRIDEF;
        float sy = (float)h * STRIDEF;
        float ax1 = __fadd_rn(anchors[a * 4 + 0], sx);
        float ay1 = __fadd_rn(anchors[a * 4 + 1], sy);
        float ax2 = __fadd_rn(anchors[a * 4 + 2], sx);
        float ay2 = __fadd_rn(anchors[a * 4 + 3], sy);

        float ws = __fadd_rn(__fsub_rn(ax2, ax1), 1.0f);
        float hs = __fadd_rn(__fsub_rn(ay2, ay1), 1.0f);
        float cx = __fadd_rn(ax1, __fmul_rn(0.5f, ws));
        float cy = __fadd_rn(ay1, __fmul_rn(0.5f, hs));

        size_t base = (((size_t)img * (4 * ANUM) + 4 * a) * HH + h) * WW + w;
        float dx = pred[base];
        float dy = pred[base + (size_t)HH * WW];
        float dw = pred[base + 2 * (size_t)HH * WW];
        float dh = pred[base + 3 * (size_t)HH * WW];
        const float XCLIP = 4.135166556742356f; // log(1000/16)
        dw = fminf(dw, XCLIP);
        dh = fminf(dh, XCLIP);

        float pcx = __fadd_rn(__fmul_rn(dx, ws), cx);
        float pcy = __fadd_rn(__fmul_rn(dy, hs), cy);
        float ew = (float)exp((double)dw);
        float eh = (float)exp((double)dh);
        float pw = __fmul_rn(ew, ws);
        float ph = __fmul_rn(eh, hs);

        x1 = __fsub_rn(pcx, __fmul_rn(0.5f, pw));
        y1 = __fsub_rn(pcy, __fmul_rn(0.5f, ph));
        x2 = __fsub_rn(__fadd_rn(pcx, __fmul_rn(0.5f, pw)), 1.0f);
        y2 = __fsub_rn(__fadd_rn(pcy, __fmul_rn(0.5f, ph)), 1.0f);

        float im_h = iminfo[img * 3 + 0];
        float im_w = iminfo[img * 3 + 1];
        float scale = iminfo[img * 3 + 2];
        float wmax = __fsub_rn(im_w, 1.0f);
        float hmax = __fsub_rn(im_h, 1.0f);
        x1 = fminf(fmaxf(x1, 0.0f), wmax);
        y1 = fminf(fmaxf(y1, 0.0f), hmax);
        x2 = fminf(fmaxf(x2, 0.0f), wmax);
        y2 = fminf(fmaxf(y2, 0.0f), hmax);

        float ws2 = __fadd_rn(__fsub_rn(x2, x1), 1.0f);
        float hs2 = __fadd_rn(__fsub_rn(y2, y1), 1.0f);
        float ms = __fmul_rn(0.0f, scale);   // MIN_SIZE = 0
        valid = (ws2 >= ms) & (hs2 >= ms)
              & (__fadd_rn(x1, __fmul_rn(ws2, 0.5f)) < im_w)
              & (__fadd_rn(y1, __fmul_rn(hs2, 0.5f)) < im_h);

        area = __fmul_rn(ws2, hs2);   // same rounding order as reference areas
    }

    unsigned int b = __ballot_sync(0xffffffffu, valid);
    if ((threadIdx.x & 31) == 0) g_valmask32[img][i >> 5] = b;

    if (i < PRE) {
        g_box[img][i] = make_float4(x1, y1, x2, y2);
        g_boxn[img][i] = make_float4(-x1, -y1, x2, y2);
        g_area[img][i] = area;
    }
}

// ---------------- NMS pairwise bitmask (4 rows/thread, fma screen) -----------
__global__ void k_nmsmask() {
    int img = blockIdx.z;
    int rt = blockIdx.y;                 // row tile: 256 rows
    int cb = blockIdx.x;                 // col word: 64 cols
    int t = threadIdx.x;                 // 0..63
    int j0 = cb * 64;
    int rbase = rt * ROWT;

    if (j0 + 64 <= rbase) {              // all cols <= all rows -> zero words
        #pragma unroll
        for (int r = 0; r < 4; r++) {
            int i = rbase + r * 64 + t;
            if (i < PRE) g_mask[img][i][cb] = 0ull;
        }
        return;
    }

    __shared__ float4 cb4[64];           // (-x1,-y1,x2,y2)
    __shared__ float  ca[64];
    int j = j0 + t;
    if (j < PRE) {
        cb4[t] = g_boxn[img][j];
        ca[t] = g_area[img][j];
    } else {
        cb4[t] = make_float4(-1e30f, -1e30f, -1e30f, -1e30f);
        ca[t] = 1.0f;
    }
    __syncthreads();

    float4 rb[4];
    float  ra[4];
    int    ri[4];
    #pragma unroll
    for (int r = 0; r < 4; r++) {
        ri[r] = rbase + r * 64 + t;
        if (ri[r] < PRE) {
            rb[r] = g_boxn[img][ri[r]];
            ra[r] = g_area[img][ri[r]];
        } else {
            rb[r] = make_float4(-1e30f, -1e30f, -1e30f, -1e30f);
            ra[r] = 1.0f;
        }
    }

    unsigned long long bits[4] = {0ull, 0ull, 0ull, 0ull};

    #pragma unroll 4
    for (int q = 0; q < 64; q++) {
        float4 c = cb4[q];
        float caj = ca[q];
        #pragma unroll
        for (int r = 0; r < 4; r++) {
            float e1 = fminf(rb[r].z, c.z);      // min(x2i, x2j)
            float e2 = fminf(rb[r].x, c.x);      // -max(x1i, x1j)
            float iw = __fadd_rn(__fadd_rn(e1, e2), 1.0f);
            float e3 = fminf(rb[r].w, c.w);
            float e4 = fminf(rb[r].y, c.y);
            float ih = __fadd_rn(__fadd_rn(e3, e4), 1.0f);
            iw = fmaxf(iw, 0.0f);
            ih = fmaxf(ih, 0.0f);
            float inter = __fmul_rn(iw, ih);
            float s = __fadd_rn(ra[r], caj);
            float denom = __fsub_rn(s, inter);
            float d = __fmaf_rn(-0.7f, denom, inter);
            float th = __fmul_rn(denom, 1e-5f);
            bool sup;
            if (fabsf(d) <= th || denom <= 0.0f) {
                sup = (__fdiv_rn(inter, denom) > 0.7f);     // exact ref path (rare)
            } else {
                sup = (d > 0.0f);
            }
            if (sup) bits[r] |= (1ull << q);
        }
    }

    int colend = PRE - j0;
    unsigned long long colmask = (colend >= 64) ? ~0ull : ((1ull << colend) - 1ull);
    #pragma unroll
    for (int r = 0; r < 4; r++) {
        int i = ri[r];
        if (i < PRE) {
            unsigned long long m = bits[r] & colmask;
            if (i >= j0) {
                int low = i - j0 + 1;
                m = (low >= 64) ? 0ull : (m & ~((1ull << low) - 1ull));
            }
            g_mask[img][i][cb] = m;
        }
    }
}

// ---------------- greedy reduce: replicated-cur, ALU-only critical chain -----
__global__ void k_reduce() {
    int img = blockIdx.x;
    int t = threadIdx.x;                 // 0..31
    unsigned int v0 = g_valmask32[img][2 * t];
    unsigned int v1 = g_valmask32[img][2 * t + 1];
    unsigned long long rem = ~(((unsigned long long)v1 << 32) | (unsigned long long)v0);

    const unsigned long long* mrow = &g_mask[img][0][t];   // stride 32 u64

    unsigned long long buf[16];
    #pragma unroll
    for (int k = 0; k < 16; k++) buf[k] = mrow[k * 32];

    unsigned long long keepw = 0ull;
    unsigned long long cur = __shfl_sync(0xffffffffu, rem, 0);

    for (int g = 0; g < 125; g++) {
        unsigned long long nbuf[16];
        if (g < 124) {
            #pragma unroll
            for (int k = 0; k < 16; k++) nbuf[k] = mrow[(g + 1) * 512 + k * 32];
        }
        int base = g * 16;
        int c = base >> 6;
        #pragma unroll
        for (int k = 0; k < 16; k++) {
            int q = (base + k) & 63;
            unsigned long long mb = __shfl_sync(0xffffffffu, buf[k], c);
            bool sup = (cur >> q) & 1ull;
            if (!sup) {
                rem |= buf[k];
                cur |= mb;
                keepw |= (1ull << q);
            }
        }
        if (((base + 16) & 63) == 0) {   // end of a 64-chunk
            if (t == 0) g_keepw[img][c] = keepw;
            keepw = 0ull;
            if (c + 1 < NWORDS) cur = __shfl_sync(0xffffffffu, rem, c + 1);
        }
        #pragma unroll
        for (int k = 0; k < 16; k++) buf[k] = nbuf[k];
    }
    if (t == 0) g_keepw[img][31] = keepw;   // partial last chunk (i 1984..1999)
}

// ---------------- stable compaction + output (popcount ranks) ----------------
__global__ void k_out(float* __restrict__ out) {
    int img = blockIdx.x;
    int tid = threadIdx.x;               // 1024 threads
    __shared__ unsigned long long kw[NWORDS];
    __shared__ int woff[NWORDS + 1];

    if (tid < NWORDS) kw[tid] = g_keepw[img][tid];
    __syncthreads();
    if (tid < NWORDS) {
        int x = __popcll(kw[tid]);
        #pragma unroll
        for (int o = 1; o < 32; o <<= 1) {
            int y = __shfl_up_sync(0xffffffffu, x, o);
            if (tid >= o) x += y;
        }
        woff[tid + 1] = x;
        if (tid == 0) woff[0] = 0;
    }
    __syncthreads();

    int total = woff[NWORDS];
    if (total > POST) total = POST;

    float* rois = out;                              // (B*POST, 5)
    float* probs = out + (size_t)BATCH * POST * 5;

    for (int i = tid; i < PRE; i += blockDim.x) {
        unsigned long long w = kw[i >> 6];
        if ((w >> (i & 63)) & 1ull) {
            int s = woff[i >> 6] + __popcll(w & ((1ull << (i & 63)) - 1ull));
            if (s < POST) {
                float4 b = g_box[img][i];
                size_t row = (size_t)(img * POST + s) * 5;
                rois[row + 0] = (float)img;
                rois[row + 1] = b.x;
                rois[row + 2] = b.y;
                rois[row + 3] = b.z;
                rois[row + 4] = b.w;
                probs[img * POST + s] = g_tsc[img][i];
            }
        }
    }
    for (int s = total + tid; s < POST; s += blockDim.x) {
        size_t row = (size_t)(img * POST + s) * 5;
        rois[row + 0] = (float)img;
        rois[row + 1] = 0.0f;
        rois[row + 2] = 0.0f;
        rois[row + 3] = 0.0f;
        rois[row + 4] = 0.0f;
        probs[img * POST + s] = 0.0f;
    }
}

// ---------------- launch ----------------
extern "C" void kernel_launch(void* const* d_in, const int* in_sizes, int n_in,
                              void* d_out, int out_size) {
    const float* cls     = (const float*)d_in[0];
    const float* pred    = (const float*)d_in[1];
    const float* iminfo  = (const float*)d_in[2];
    const float* anchors = (const float*)d_in[3];
    float* out = (float*)d_out;

    k_init<<<BATCH, 256>>>();
    k_hist<<<dim3(120, BATCH), 256>>>(cls, 0);
    k_select<<<BATCH, 256>>>();
    k_hist<<<dim3(120, BATCH), 256>>>(cls, 1);
    k_select<<<BATCH, 256>>>();
    k_compact<<<dim3(120, BATCH), 256>>>(cls);
    k_sort<<<BATCH, 1024>>>();
    k_props<<<dim3(2, BATCH), 1024>>>(pred, iminfo, anchors);
    k_nmsmask<<<dim3(NWORDS, (PRE + ROWT - 1) / ROWT, BATCH), 64>>>();
    k_reduce<<<BATCH, 32>>>();
    k_out<<<BATCH, 1024>>>(out);
}